// round 4
// baseline (speedup 1.0000x reference)
#include <cuda_runtime.h>

// ---------------------------------------------------------------------------
// VectorQuantizer (VQ-VAE codebook lookup)
//   z   : [32, 256, 32, 32] fp32   (B, D, H, W)
//   emb : [1024, 256] fp32         (K, D)
// outputs (concatenated fp32 in d_out):
//   [0]                     loss (scalar)
//   [1 .. 1+8388608)        z_q_out  [B, D, H, W]
//   [8388609]               perplexity (scalar)
//   [8388610 .. +33554432)  min_encodings one-hot [N, K]
//   [41943042 .. +32768)    idx [B, H, W] (as float)
//
// Numerics: the reference evaluates d = (||z||^2 + ||e||^2) - 2 z.e in fp32 at
// magnitude ~256 (ulp 3e-5), quantizing near-ties into exact fp32 ties that
// argmin breaks by first index. We replicate: zz with XLA row-reduce order,
// dot as a sequential-k FFMA chain, final value rounded the same way, and
// first-occurrence argmin.
// ---------------------------------------------------------------------------

#define Dd     256
#define Kk     1024
#define NTOK   32768          // 32 * 32 * 32
#define NELEM  8388608        // NTOK * Dd

#define OFF_LOSS 0
#define OFF_ZQ   1
#define OFF_PERP 8388609
#define OFF_ME   8388610
#define OFF_IDX  41943042

// scratch (static device globals -- no allocation allowed)
__device__ float g_enorm[Kk];
__device__ float g_znorm[NTOK];
__device__ int   g_idx[NTOK];
__device__ int   g_count[Kk];
__device__ float g_partial[8192];

// ---------------------------------------------------------------------------
__global__ void reset_kernel() {
    int t = threadIdx.x;
    if (t < Kk) g_count[t] = 0;
}

// ---------------------------------------------------------------------------
// ||e_k||^2 per code. (e-norm bits never matter: ee << half-ulp(zz), so the
// reference's RN(zz+ee) == zz; any accumulation order is fine here.)
// ---------------------------------------------------------------------------
__global__ void enorm_kernel(const float* __restrict__ emb) {
    int k    = blockIdx.x;
    int lane = threadIdx.x;
    const float4* row = (const float4*)(emb + (size_t)k * Dd);
    float4 a = row[lane];
    float4 b = row[32 + lane];
    float s = a.x*a.x + a.y*a.y + a.z*a.z + a.w*a.w
            + b.x*b.x + b.y*b.y + b.z*b.z + b.w*b.w;
    #pragma unroll
    for (int o = 16; o > 0; o >>= 1)
        s += __shfl_xor_sync(0xFFFFFFFFu, s, o);
    if (lane == 0) g_enorm[k] = s;
}

// ---------------------------------------------------------------------------
// ||z_n||^2 per token, replicating XLA:GPU fp32 row reduction on the
// materialized zf [N, 256] row:
//   lane t: acc = ((x[t]^2 + x[t+32]^2) + x[t+64]^2) + ... (8 terms, mul then
//   add, both individually rounded), then shfl-down tree offsets 16,8,4,2,1.
// Block = 256 threads handles 32 tokens of one batch image; z tile staged
// through smem for coalescing (z is [B,D,H,W]: token dim has stride 1).
// ---------------------------------------------------------------------------
__global__ __launch_bounds__(256)
void znorm_kernel(const float* __restrict__ z) {
    __shared__ float zs[256 * 33];           // [d][r], stride 33
    const int n0 = blockIdx.x * 32;          // 32 tokens per block
    const int b  = n0 >> 10;
    const int r0 = n0 & 1023;
    const float* zb = z + (size_t)b * (Dd * 1024) + r0;

    const int tid = threadIdx.x;
    const int lr  = tid & 31;                // token-in-tile
    const int dg  = tid >> 5;                // 0..7
    #pragma unroll
    for (int dd = 0; dd < 256; dd += 8)
        zs[(dd + dg) * 33 + lr] = __ldg(zb + (size_t)(dd + dg) * 1024 + lr);
    __syncthreads();

    const int w = tid >> 5;                  // warp 0..7
    const int t = tid & 31;                  // lane
    #pragma unroll
    for (int q = 0; q < 4; ++q) {
        const int tok = w * 4 + q;           // 0..31
        float acc = 0.0f;
        #pragma unroll
        for (int i = 0; i < 8; ++i) {
            float x = zs[(t + 32 * i) * 33 + tok];
            acc = __fadd_rn(acc, __fmul_rn(x, x));
        }
        #pragma unroll
        for (int o = 16; o > 0; o >>= 1)
            acc = __fadd_rn(acc, __shfl_down_sync(0xFFFFFFFFu, acc, o));
        if (t == 0) g_znorm[n0 + tok] = acc;
    }
}

// ---------------------------------------------------------------------------
// argmin kernel: per token n, argmin_k RN( RN(zz_n + ee_k) - 2 * dot_nk )
// dot accumulated as a sequential FFMA chain over k = 0..255 (SGEMM order).
// block = 256 threads, TM=64 tokens x TK=64 codes, D chunked by 32.
// ---------------------------------------------------------------------------
#define TM 64
#define TK 64
#define DK 32
#define ZS 68   // padded stride (floats)

__global__ __launch_bounds__(256, 4)
void argmin_kernel(const float* __restrict__ z,
                   const float* __restrict__ emb,
                   float* __restrict__ out_idx)   // d_out + OFF_IDX
{
    __shared__ float z_s[DK * ZS];
    __shared__ float e_s[DK * ZS];
    __shared__ float en_s[TK];
    __shared__ float zz_s[TM];
    __shared__ float red_v[TM * 16];
    __shared__ int   red_i[TM * 16];
    __shared__ float min_v[TM];
    __shared__ int   min_i[TM];

    const int tid = threadIdx.x;
    const int tx  = tid & 15;
    const int ty  = tid >> 4;

    const int n0 = blockIdx.x * TM;
    const int bb = n0 >> 10;
    const int r0 = n0 & 1023;
    const float* zb = z + (size_t)bb * (Dd * 1024) + r0;

    if (tid < TM) {
        min_v[tid] = 3.4e38f;
        min_i[tid] = 0;
        zz_s[tid]  = g_znorm[n0 + tid];
    }

    for (int kb = 0; kb < Kk / TK; ++kb) {
        const int k0 = kb * TK;
        __syncthreads();
        if (tid < TK) en_s[tid] = g_enorm[k0 + tid];

        float acc[4][4];
        #pragma unroll
        for (int i = 0; i < 4; ++i)
            #pragma unroll
            for (int j = 0; j < 4; ++j) acc[i][j] = 0.0f;

        for (int db = 0; db < Dd / DK; ++db) {
            __syncthreads();
            // ---- load z tile [DK][TM]
            {
                const int t  = tid & 63;
                const int dg = tid >> 6;
                #pragma unroll
                for (int i = 0; i < 8; ++i) {
                    const int dl = dg * 8 + i;
                    z_s[dl * ZS + t] = __ldg(zb + (size_t)(db * DK + dl) * 1024 + t);
                }
            }
            // ---- load e tile [DK][TK] transposed
            {
                const int c = tid >> 2;
                const int q = tid & 3;
                const float4* erow =
                    (const float4*)(emb + (size_t)(k0 + c) * Dd + db * DK);
                float4 e0 = __ldg(&erow[q]);
                float4 e1 = __ldg(&erow[4 + q]);
                e_s[(q*4+0) * ZS + c] = e0.x;
                e_s[(q*4+1) * ZS + c] = e0.y;
                e_s[(q*4+2) * ZS + c] = e0.z;
                e_s[(q*4+3) * ZS + c] = e0.w;
                e_s[(16+q*4+0) * ZS + c] = e1.x;
                e_s[(16+q*4+1) * ZS + c] = e1.y;
                e_s[(16+q*4+2) * ZS + c] = e1.z;
                e_s[(16+q*4+3) * ZS + c] = e1.w;
            }
            __syncthreads();
            // ---- FMA 4x4 micro-tile, k strictly ascending (SGEMM chain)
            #pragma unroll
            for (int kkk = 0; kkk < DK; ++kkk) {
                float4 zv = *(const float4*)(z_s + kkk * ZS + ty * 4);
                float4 ev = *(const float4*)(e_s + kkk * ZS + tx * 4);
                float az[4] = {zv.x, zv.y, zv.z, zv.w};
                float be[4] = {ev.x, ev.y, ev.z, ev.w};
                #pragma unroll
                for (int i = 0; i < 4; ++i)
                    #pragma unroll
                    for (int j = 0; j < 4; ++j)
                        acc[i][j] = __fmaf_rn(az[i], be[j], acc[i][j]);
            }
        }

        // ---- reference-rounded distance + first-occurrence local argmin
        #pragma unroll
        for (int i = 0; i < 4; ++i) {
            const float zz = zz_s[ty * 4 + i];
            float bv = 3.4e38f;
            int   bj = 0;
            #pragma unroll
            for (int j = 0; j < 4; ++j) {
                float t1 = __fadd_rn(zz, en_s[tx * 4 + j]);   // == zz (ee << ulp)
                float v  = __fmaf_rn(-2.0f, acc[i][j], t1);   // RN(t1 - 2*dot)
                if (v < bv) { bv = v; bj = j; }
            }
            red_v[(ty * 4 + i) * 16 + tx] = bv;
            red_i[(ty * 4 + i) * 16 + tx] = k0 + tx * 4 + bj;
        }
        __syncthreads();
        // ---- per-token reduce, ascending tx = ascending code index
        if (tid < TM) {
            float bv = min_v[tid];
            int   bi = min_i[tid];
            #pragma unroll
            for (int x = 0; x < 16; ++x) {
                float v = red_v[tid * 16 + x];
                if (v < bv) { bv = v; bi = red_i[tid * 16 + x]; }
            }
            min_v[tid] = bv;
            min_i[tid] = bi;
        }
    }

    if (tid < TM) {
        const int n  = n0 + tid;
        const int bi = min_i[tid];
        g_idx[n]   = bi;
        out_idx[n] = (float)bi;
        atomicAdd(&g_count[bi], 1);
    }
}

// ---------------------------------------------------------------------------
__global__ void zero_me_kernel(float* __restrict__ me) {
    float2* p = (float2*)me;
    const int g = blockIdx.x * 256 + threadIdx.x;
    #pragma unroll
    for (int i = 0; i < 8; ++i)
        p[g + i * 2097152] = make_float2(0.0f, 0.0f);
}

__global__ void ones_kernel(float* __restrict__ me) {
    const int n = blockIdx.x * 256 + threadIdx.x;
    me[(size_t)n * Kk + g_idx[n]] = 1.0f;
}

// ---------------------------------------------------------------------------
__global__ __launch_bounds__(256)
void zq_loss_kernel(const float* __restrict__ z,
                    const float* __restrict__ emb,
                    float* __restrict__ zq_out)
{
    __shared__ float red[256];
    const int g    = blockIdx.x * 256 + threadIdx.x;
    const int flat = g * 4;
    const int d    = (flat >> 10) & 255;
    const int b    = flat >> 18;
    const int rem  = flat & 1023;
    const int n    = b * 1024 + rem;

    float4 zv = *(const float4*)(z + flat);

    float q0 = emb[(size_t)g_idx[n + 0] * Dd + d];
    float q1 = emb[(size_t)g_idx[n + 1] * Dd + d];
    float q2 = emb[(size_t)g_idx[n + 2] * Dd + d];
    float q3 = emb[(size_t)g_idx[n + 3] * Dd + d];

    zq_out[flat + 0] = q0;
    zq_out[flat + 1] = q1;
    zq_out[flat + 2] = q2;
    zq_out[flat + 3] = q3;

    float d0 = q0 - zv.x, d1 = q1 - zv.y, d2 = q2 - zv.z, d3 = q3 - zv.w;
    float s = d0*d0 + d1*d1 + d2*d2 + d3*d3;

    red[threadIdx.x] = s;
    __syncthreads();
    #pragma unroll
    for (int o = 128; o > 0; o >>= 1) {
        if (threadIdx.x < o) red[threadIdx.x] += red[threadIdx.x + o];
        __syncthreads();
    }
    if (threadIdx.x == 0) g_partial[blockIdx.x] = red[0];
}

// ---------------------------------------------------------------------------
__global__ void finalize_kernel(float* __restrict__ out) {
    __shared__ float sdata[1024];
    const int t = threadIdx.x;

    float s = 0.0f;
    #pragma unroll
    for (int i = 0; i < 8; ++i) s += g_partial[t + i * 1024];
    sdata[t] = s;
    __syncthreads();
    #pragma unroll
    for (int o = 512; o > 0; o >>= 1) {
        if (t < o) sdata[t] += sdata[t + o];
        __syncthreads();
    }
    if (t == 0) out[OFF_LOSS] = 1.25f * sdata[0] / (float)NELEM;
    __syncthreads();

    float em   = (float)g_count[t] * (1.0f / (float)NTOK);
    sdata[t]   = em * logf(em + 1e-10f);
    __syncthreads();
    #pragma unroll
    for (int o = 512; o > 0; o >>= 1) {
        if (t < o) sdata[t] += sdata[t + o];
        __syncthreads();
    }
    if (t == 0) out[OFF_PERP] = expf(-sdata[0]);
}

// ---------------------------------------------------------------------------
extern "C" void kernel_launch(void* const* d_in, const int* in_sizes, int n_in,
                              void* d_out, int out_size)
{
    const float* z   = (const float*)d_in[0];
    const float* emb = (const float*)d_in[1];
    float*       o   = (float*)d_out;

    reset_kernel<<<1, 1024>>>();
    enorm_kernel<<<Kk, 32>>>(emb);
    znorm_kernel<<<NTOK / 32, 256>>>(z);
    zero_me_kernel<<<8192, 256>>>(o + OFF_ME);
    argmin_kernel<<<NTOK / TM, 256>>>(z, emb, o + OFF_IDX);
    ones_kernel<<<NTOK / 256, 256>>>(o + OFF_ME);
    zq_loss_kernel<<<NELEM / 1024, 256>>>(z, emb, o + OFF_ZQ);
    finalize_kernel<<<1, 1024>>>(o);
}